// round 10
// baseline (speedup 1.0000x reference)
#include <cuda_runtime.h>
#include <cstdint>

// GatingNetwork: B=4096 tokens, x=concat(t1,t2) -> K=2048, E=64 experts.
// logits[b,e] = -sqrt(||w_e - x_b||^2); top-2 softmax scattered into (B,E).
//
// Round 9: mma.sync bf16-split GEMM, 512 threads / 16 warps,
// 2 chunks per barrier (16 sync iterations), W 8-stage cp.async pipeline
// with uniform commit groups (empty at tail), X 4-deep register prefetch.
// dot = xh*wh + xh*wl + xl*wh in fp32; exact fp32 ||x||^2 / ||w||^2.

#define B_TOK   4096
#define D_HALF  1024
#define KDIM    2048
#define NEXP    64
#define TILE_M  32
#define KC      64
#define NCHUNK  (KDIM / KC)       // 32
#define NITER   (NCHUNK / 2)      // 16
#define NTHR    512
#define WSTAGES 8
#define XSTAGES 4

#define RPITCH  144               // 64 bf16 = 128B + 16B pad (LDSM conflict-free)
#define XSTG_B  (2 * TILE_M * RPITCH)         // 9216 (hi+lo, 32 rows)
#define XH_OFF  0
#define XL_OFF  (TILE_M * RPITCH)             // 4608
#define WSTG_B  (2 * NEXP * RPITCH)           // 18432
#define WH_OFF  0
#define WL_OFF  (NEXP * RPITCH)               // 9216
#define WBASE   (XSTAGES * XSTG_B)            // 36864
#define SMEM_TOTAL (WBASE + WSTAGES * WSTG_B) // 184320
#define DP      68                // dots pitch (floats)

__device__ uint32_t g_wh[NEXP * KDIM / 2];   // bf16x2 packed
__device__ uint32_t g_wl[NEXP * KDIM / 2];
__device__ float    g_wsq[NEXP];

// ---------------------------------------------------------------------------
__device__ __forceinline__ uint32_t smem_u32(const void* p) {
    uint32_t a;
    asm("{ .reg .u64 t; cvta.to.shared.u64 t, %1; cvt.u32.u64 %0, t; }"
        : "=r"(a) : "l"(p));
    return a;
}
__device__ __forceinline__ void cp16(uint32_t dst, const void* src) {
    asm volatile("cp.async.cg.shared.global [%0], [%1], 16;" :: "r"(dst), "l"(src));
}
__device__ __forceinline__ void cp_commit() { asm volatile("cp.async.commit_group;"); }
template <int N>
__device__ __forceinline__ void cp_wait() {
    asm volatile("cp.async.wait_group %0;" :: "n"(N));
}
__device__ __forceinline__ uint32_t pack_bf2(float lo, float hi) {
    uint32_t d;
    asm("cvt.rn.bf16x2.f32 %0, %1, %2;" : "=r"(d) : "f"(hi), "f"(lo));
    return d;
}
__device__ __forceinline__ void sts64(uint32_t a, uint32_t v0, uint32_t v1) {
    asm volatile("st.shared.v2.b32 [%0], {%1,%2};"
                 :: "r"(a), "r"(v0), "r"(v1) : "memory");
}

#define LDSM4(r, addr) \
    asm volatile("ldmatrix.sync.aligned.m8n8.x4.shared.b16 {%0,%1,%2,%3}, [%4];" \
        : "=r"((r)[0]), "=r"((r)[1]), "=r"((r)[2]), "=r"((r)[3]) : "r"(addr))

#define MMA(c, a, b0_, b1_) \
    asm volatile("mma.sync.aligned.m16n8k16.row.col.f32.bf16.bf16.f32 " \
        "{%0,%1,%2,%3}, {%4,%5,%6,%7}, {%8,%9}, {%0,%1,%2,%3};" \
        : "+f"((c)[0]), "+f"((c)[1]), "+f"((c)[2]), "+f"((c)[3]) \
        : "r"((a)[0]), "r"((a)[1]), "r"((a)[2]), "r"((a)[3]), "r"(b0_), "r"(b1_))

__device__ __forceinline__ bool sless(float a, int ia, float b, int ib) {
    return (a < b) || (a == b && ia < ib);
}

// ---------------------------------------------------------------------------
// Kernel 1: split W into bf16 hi/lo, exact ||w||^2.
// ---------------------------------------------------------------------------
__global__ __launch_bounds__(256) void wsplit_kernel(const float* __restrict__ w) {
    const int row = blockIdx.x;
    const int t = threadIdx.x;
    const float4* src = (const float4*)(w + (size_t)row * KDIM);
    float q = 0.f;
    for (int i = t; i < KDIM / 4; i += 256) {
        float4 v = src[i];
        uint32_t h0 = pack_bf2(v.x, v.y);
        uint32_t h1 = pack_bf2(v.z, v.w);
        float r0 = v.x - __uint_as_float(h0 << 16);
        float r1 = v.y - __uint_as_float(h0 & 0xffff0000u);
        float r2 = v.z - __uint_as_float(h1 << 16);
        float r3 = v.w - __uint_as_float(h1 & 0xffff0000u);
        uint32_t l0 = pack_bf2(r0, r1);
        uint32_t l1 = pack_bf2(r2, r3);
        q = fmaf(v.x, v.x, q); q = fmaf(v.y, v.y, q);
        q = fmaf(v.z, v.z, q); q = fmaf(v.w, v.w, q);
        g_wh[row * (KDIM / 2) + 2 * i]     = h0;
        g_wh[row * (KDIM / 2) + 2 * i + 1] = h1;
        g_wl[row * (KDIM / 2) + 2 * i]     = l0;
        g_wl[row * (KDIM / 2) + 2 * i + 1] = l1;
    }
#pragma unroll
    for (int o = 16; o; o >>= 1) q += __shfl_xor_sync(0xffffffffu, q, o);
    __shared__ float red[8];
    if ((t & 31) == 0) red[t >> 5] = q;
    __syncthreads();
    if (t == 0) {
        float s = 0.f;
#pragma unroll
        for (int i = 0; i < 8; i++) s += red[i];
        g_wsq[row] = s;
    }
}

// ---------------------------------------------------------------------------
// Kernel 2: fused GEMM + top-2 + softmax + scatter.
// CTA = 32 tokens x 64 experts x K=2048. 16 warps: (wm, wn2, wk).
// ---------------------------------------------------------------------------
__global__ __launch_bounds__(NTHR) void gemm_kernel(const float* __restrict__ t1,
                                                    const float* __restrict__ t2,
                                                    float* __restrict__ out) {
    extern __shared__ char smem[];
    const uint32_t sb = smem_u32(smem);
    const int tid  = threadIdx.x;
    const int lane = tid & 31;
    const int wid  = tid >> 5;
    const int wk   = wid & 3;        // k16 slice within a chunk
    const int wn2  = (wid >> 2) & 1; // n32 half
    const int wm   = wid >> 3;       // m16 half
    const int tokBase = blockIdx.x * TILE_M;

    const uint32_t aoff = (uint32_t)((wm * 16 + (lane & 15)) * RPITCH
                                     + (lane >> 4) * 16 + wk * 32);
    const uint32_t boff0 = (uint32_t)((wn2 * 32 + ((lane & 7) | ((lane >> 4) << 3))) * RPITCH
                                      + ((lane >> 3) & 1) * 16 + wk * 32);
    const uint32_t boff1 = boff0 + 16 * RPITCH;

    const int xr = tid >> 4;        // X staging row 0..31
    const int xs = tid & 15;        // 4-float segment

    float acc[4][4];
#pragma unroll
    for (int i = 0; i < 4; i++)
#pragma unroll
        for (int j = 0; j < 4; j++) acc[i][j] = 0.f;
    float xq = 0.f;
    float4 rx0, rx1, rx2, rx3;      // X prefetch, 4 chunks deep

    auto ldgX = [&](float4& dst, int chunk) {
        const int k0 = chunk * KC;
        const float* xsrc = (k0 < D_HALF) ? t1 : t2;
        const int kx = k0 & (D_HALF - 1);
        dst = *(const float4*)(xsrc + (size_t)(tokBase + xr) * D_HALF + kx + xs * 4);
    };
    auto stsX = [&](const float4& v, int buf) {
        uint32_t h0 = pack_bf2(v.x, v.y);
        uint32_t h1 = pack_bf2(v.z, v.w);
        uint32_t l0 = pack_bf2(v.x - __uint_as_float(h0 << 16),
                               v.y - __uint_as_float(h0 & 0xffff0000u));
        uint32_t l1 = pack_bf2(v.z - __uint_as_float(h1 << 16),
                               v.w - __uint_as_float(h1 & 0xffff0000u));
        xq = fmaf(v.x, v.x, xq); xq = fmaf(v.y, v.y, xq);
        xq = fmaf(v.z, v.z, xq); xq = fmaf(v.w, v.w, xq);
        uint32_t xb = sb + (uint32_t)buf * XSTG_B + (uint32_t)(xr * RPITCH + xs * 8);
        sts64(xb + XH_OFF, h0, h1);
        sts64(xb + XL_OFF, l0, l1);
    };
    // One commit group per chunk, ALWAYS committed (empty at tail) so the
    // cp_wait<4> group arithmetic stays uniform across the whole loop.
    auto cpW = [&](int chunk) {
        if (chunk < NCHUNK) {
            const int k0 = chunk * KC;
            const uint32_t wb = sb + WBASE + (uint32_t)(chunk & (WSTAGES - 1)) * WSTG_B;
#pragma unroll
            for (int j = 0; j < 2; j++) {
                int i = tid + NTHR * j;           // 0..1023
                int half = i >> 9;                // 0: hi, 1: lo
                int r = (i >> 3) & 63;
                int c = i & 7;
                const uint32_t* srcb = half ? g_wl : g_wh;
                cp16(wb + (half ? WL_OFF : WH_OFF) + (uint32_t)(r * RPITCH + c * 16),
                     srcb + ((size_t)r * (KDIM / 2) + (k0 >> 1) + c * 4));
            }
        }
        cp_commit();
    };
    auto compute = [&](int chunk) {
        const uint32_t xb = sb + (uint32_t)(chunk & (XSTAGES - 1)) * XSTG_B;
        const uint32_t wb = sb + WBASE + (uint32_t)(chunk & (WSTAGES - 1)) * WSTG_B;
        uint32_t ah[4], al[4], bh0[4], bh1[4], bl0[4], bl1[4];
        LDSM4(ah,  xb + XH_OFF + aoff);
        LDSM4(bh0, wb + WH_OFF + boff0);
        LDSM4(bh1, wb + WH_OFF + boff1);
        LDSM4(al,  xb + XL_OFF + aoff);
        LDSM4(bl0, wb + WL_OFF + boff0);
        LDSM4(bl1, wb + WL_OFF + boff1);
        MMA(acc[0], ah, bh0[0], bh0[1]);
        MMA(acc[1], ah, bh0[2], bh0[3]);
        MMA(acc[2], ah, bh1[0], bh1[1]);
        MMA(acc[3], ah, bh1[2], bh1[3]);
        MMA(acc[0], al, bh0[0], bh0[1]);
        MMA(acc[1], al, bh0[2], bh0[3]);
        MMA(acc[2], al, bh1[0], bh1[1]);
        MMA(acc[3], al, bh1[2], bh1[3]);
        MMA(acc[0], ah, bl0[0], bl0[1]);
        MMA(acc[1], ah, bl0[2], bl0[3]);
        MMA(acc[2], ah, bl1[0], bl1[1]);
        MMA(acc[3], ah, bl1[2], bl1[3]);
    };

    // prologue: X regs for chunks 0..3; W groups for chunks 0..5
    ldgX(rx0, 0); ldgX(rx1, 1); ldgX(rx2, 2); ldgX(rx3, 3);
    cpW(0); cpW(1); cpW(2); cpW(3); cpW(4); cpW(5);

    for (int it = 0; it < NITER; it++) {
        const int c0 = 2 * it, c1 = c0 + 1;
        // stage X for chunks c0, c1 (buffers (c0&3),(c1&3); prior readers
        // finished before the previous barrier)
        stsX(rx0, c0 & 3);
        stsX(rx1, c1 & 3);
        rx0 = rx2; rx1 = rx3;
        if (c0 + 4 < NCHUNK) ldgX(rx2, c0 + 4);
        if (c0 + 5 < NCHUNK) ldgX(rx3, c0 + 5);

        cp_wait<4>();            // groups <= c1 complete (uniform commit count)
        __syncthreads();         // X(c0,c1) + W(c0,c1) visible to all warps
        cpW(c0 + 6);             // target buffers' readers (c0-2,c1-2) done
        cpW(c0 + 7);

        compute(c0);
        compute(c1);
    }
    __syncthreads();             // all compute done before smem reuse

    // ---- epilogue: K-split partial dots -> smem, sum, top-2, scatter ----
    float* kd  = (float*)smem;                 // [4][32][DP]
    float* sxq = kd + 4 * TILE_M * DP;         // [32]

    {
        int r0 = wm * 16 + (lane >> 2);
        int cb = wn2 * 32 + (lane & 3) * 2;
#pragma unroll
        for (int t = 0; t < 2; t++)
#pragma unroll
            for (int j = 0; j < 2; j++) {
                const float* a = acc[t * 2 + j];
                int cc = cb + t * 16 + j * 8;
                kd[(wk * TILE_M + r0) * DP + cc]           = a[0];
                kd[(wk * TILE_M + r0) * DP + cc + 1]       = a[1];
                kd[(wk * TILE_M + r0 + 8) * DP + cc]       = a[2];
                kd[(wk * TILE_M + r0 + 8) * DP + cc + 1]   = a[3];
            }
    }
#pragma unroll
    for (int o = 8; o; o >>= 1) xq += __shfl_xor_sync(0xffffffffu, xq, o);
    if ((tid & 15) == 0) sxq[xr] = xq;
    __syncthreads();

    const float w0 = g_wsq[lane];
    const float w1 = g_wsq[lane + 32];
    const int e0 = lane, e1 = lane + 32;

#pragma unroll
    for (int tt = 0; tt < 2; tt++) {
        const int rloc = wid * 2 + tt;
        const int tok = tokBase + rloc;
        float d0 = (kd[(0 * TILE_M + rloc) * DP + e0] + kd[(1 * TILE_M + rloc) * DP + e0])
                 + (kd[(2 * TILE_M + rloc) * DP + e0] + kd[(3 * TILE_M + rloc) * DP + e0]);
        float d1 = (kd[(0 * TILE_M + rloc) * DP + e1] + kd[(1 * TILE_M + rloc) * DP + e1])
                 + (kd[(2 * TILE_M + rloc) * DP + e1] + kd[(3 * TILE_M + rloc) * DP + e1]);
        float p0 = fmaf(-2.f, d0, w0);
        float p1 = fmaf(-2.f, d1, w1);

        float v1, v2; int i1, i2;
        if (sless(p0, e0, p1, e1)) { v1 = p0; i1 = e0; v2 = p1; i2 = e1; }
        else                        { v1 = p1; i1 = e1; v2 = p0; i2 = e0; }
#pragma unroll
        for (int off = 16; off > 0; off >>= 1) {
            float u1 = __shfl_xor_sync(0xffffffffu, v1, off);
            int   j1 = __shfl_xor_sync(0xffffffffu, i1, off);
            float u2 = __shfl_xor_sync(0xffffffffu, v2, off);
            int   j2 = __shfl_xor_sync(0xffffffffu, i2, off);
            float n1, n2; int m1, m2;
            if (sless(u1, j1, v1, i1)) {
                n1 = u1; m1 = j1;
                if (sless(v1, i1, u2, j2)) { n2 = v1; m2 = i1; }
                else                        { n2 = u2; m2 = j2; }
            } else {
                n1 = v1; m1 = i1;
                if (sless(u1, j1, v2, i2)) { n2 = u1; m2 = j1; }
                else                        { n2 = v2; m2 = i2; }
            }
            v1 = n1; i1 = m1; v2 = n2; i2 = m2;
        }

        const float xqv = sxq[rloc];
        float s1 = xqv + v1; s1 = s1 > 0.f ? s1 : 0.f;
        float s2 = xqv + v2; s2 = s2 > 0.f ? s2 : 0.f;
        const float lg1 = -__fsqrt_rn(s1);
        const float lg2 = -__fsqrt_rn(s2);
        const float ed  = __expf(lg2 - lg1);
        const float inv = 1.f / (1.f + ed);
        const float ga  = inv;
        const float gb  = ed * inv;

        float o0 = (e0 == i1) ? ga : ((e0 == i2) ? gb : 0.f);
        float o1 = (e1 == i1) ? ga : ((e1 == i2) ? gb : 0.f);
        out[(size_t)tok * NEXP + e0] = o0;
        out[(size_t)tok * NEXP + e1] = o1;
    }
}

// ---------------------------------------------------------------------------
extern "C" void kernel_launch(void* const* d_in, const int* in_sizes, int n_in,
                              void* d_out, int out_size) {
    const float* t1 = (const float*)d_in[0];
    const float* t2 = (const float*)d_in[1];
    const float* w  = (const float*)d_in[2];
    float* out = (float*)d_out;

    cudaFuncSetAttribute(gemm_kernel,
                         cudaFuncAttributeMaxDynamicSharedMemorySize, SMEM_TOTAL);

    wsplit_kernel<<<NEXP, 256>>>(w);
    gemm_kernel<<<B_TOK / TILE_M, NTHR, SMEM_TOTAL>>>(t1, t2, out);
}

// round 11
// speedup vs baseline: 1.0585x; 1.0585x over previous
#include <cuda_runtime.h>
#include <cstdint>

// GatingNetwork: B=4096 tokens, x=concat(t1,t2) -> K=2048, E=64 experts.
// logits[b,e] = -sqrt(||w_e - x_b||^2); top-2 softmax scattered into (B,E).
//
// Round 10: mma.sync bf16-split GEMM, 1024 threads / 32 warps (8/SMSP).
// Warp = (m16 half) x (n32 half) x (one of 8 k16 slices of a 128-wide
// chunk pair). Same smem/MMA volume as R9, double the latency hiding.
// dot = xh*wh + xh*wl + xl*wh in fp32; exact fp32 ||x||^2 / ||w||^2.

#define B_TOK   4096
#define D_HALF  1024
#define KDIM    2048
#define NEXP    64
#define TILE_M  32
#define KC      64
#define NCHUNK  (KDIM / KC)       // 32
#define NITER   (NCHUNK / 2)      // 16
#define NTHR    1024
#define WSTAGES 8
#define XSTAGES 4

#define RPITCH  144               // 64 bf16 = 128B + 16B pad (LDSM conflict-free)
#define XSTG_B  (2 * TILE_M * RPITCH)         // 9216 (hi+lo, 32 rows)
#define XH_OFF  0
#define XL_OFF  (TILE_M * RPITCH)             // 4608
#define WSTG_B  (2 * NEXP * RPITCH)           // 18432
#define WH_OFF  0
#define WL_OFF  (NEXP * RPITCH)               // 9216
#define WBASE   (XSTAGES * XSTG_B)            // 36864
#define SMEM_TOTAL (WBASE + WSTAGES * WSTG_B) // 184320
#define DP      68                // dots pitch (floats)

__device__ uint32_t g_wh[NEXP * KDIM / 2];   // bf16x2 packed
__device__ uint32_t g_wl[NEXP * KDIM / 2];
__device__ float    g_wsq[NEXP];

// ---------------------------------------------------------------------------
__device__ __forceinline__ uint32_t smem_u32(const void* p) {
    uint32_t a;
    asm("{ .reg .u64 t; cvta.to.shared.u64 t, %1; cvt.u32.u64 %0, t; }"
        : "=r"(a) : "l"(p));
    return a;
}
__device__ __forceinline__ void cp16(uint32_t dst, const void* src) {
    asm volatile("cp.async.cg.shared.global [%0], [%1], 16;" :: "r"(dst), "l"(src));
}
__device__ __forceinline__ void cp_commit() { asm volatile("cp.async.commit_group;"); }
template <int N>
__device__ __forceinline__ void cp_wait() {
    asm volatile("cp.async.wait_group %0;" :: "n"(N));
}
__device__ __forceinline__ uint32_t pack_bf2(float lo, float hi) {
    uint32_t d;
    asm("cvt.rn.bf16x2.f32 %0, %1, %2;" : "=r"(d) : "f"(hi), "f"(lo));
    return d;
}
__device__ __forceinline__ void sts64(uint32_t a, uint32_t v0, uint32_t v1) {
    asm volatile("st.shared.v2.b32 [%0], {%1,%2};"
                 :: "r"(a), "r"(v0), "r"(v1) : "memory");
}

#define LDSM4(r, addr) \
    asm volatile("ldmatrix.sync.aligned.m8n8.x4.shared.b16 {%0,%1,%2,%3}, [%4];" \
        : "=r"((r)[0]), "=r"((r)[1]), "=r"((r)[2]), "=r"((r)[3]) : "r"(addr))

#define MMA(c, a, b0_, b1_) \
    asm volatile("mma.sync.aligned.m16n8k16.row.col.f32.bf16.bf16.f32 " \
        "{%0,%1,%2,%3}, {%4,%5,%6,%7}, {%8,%9}, {%0,%1,%2,%3};" \
        : "+f"((c)[0]), "+f"((c)[1]), "+f"((c)[2]), "+f"((c)[3]) \
        : "r"((a)[0]), "r"((a)[1]), "r"((a)[2]), "r"((a)[3]), "r"(b0_), "r"(b1_))

__device__ __forceinline__ bool sless(float a, int ia, float b, int ib) {
    return (a < b) || (a == b && ia < ib);
}

// ---------------------------------------------------------------------------
// Kernel 1: split W into bf16 hi/lo, exact ||w||^2.
// ---------------------------------------------------------------------------
__global__ __launch_bounds__(256) void wsplit_kernel(const float* __restrict__ w) {
    const int row = blockIdx.x;
    const int t = threadIdx.x;
    const float4* src = (const float4*)(w + (size_t)row * KDIM);
    float q = 0.f;
    for (int i = t; i < KDIM / 4; i += 256) {
        float4 v = src[i];
        uint32_t h0 = pack_bf2(v.x, v.y);
        uint32_t h1 = pack_bf2(v.z, v.w);
        float r0 = v.x - __uint_as_float(h0 << 16);
        float r1 = v.y - __uint_as_float(h0 & 0xffff0000u);
        float r2 = v.z - __uint_as_float(h1 << 16);
        float r3 = v.w - __uint_as_float(h1 & 0xffff0000u);
        uint32_t l0 = pack_bf2(r0, r1);
        uint32_t l1 = pack_bf2(r2, r3);
        q = fmaf(v.x, v.x, q); q = fmaf(v.y, v.y, q);
        q = fmaf(v.z, v.z, q); q = fmaf(v.w, v.w, q);
        g_wh[row * (KDIM / 2) + 2 * i]     = h0;
        g_wh[row * (KDIM / 2) + 2 * i + 1] = h1;
        g_wl[row * (KDIM / 2) + 2 * i]     = l0;
        g_wl[row * (KDIM / 2) + 2 * i + 1] = l1;
    }
#pragma unroll
    for (int o = 16; o; o >>= 1) q += __shfl_xor_sync(0xffffffffu, q, o);
    __shared__ float red[8];
    if ((t & 31) == 0) red[t >> 5] = q;
    __syncthreads();
    if (t == 0) {
        float s = 0.f;
#pragma unroll
        for (int i = 0; i < 8; i++) s += red[i];
        g_wsq[row] = s;
    }
}

// ---------------------------------------------------------------------------
// Kernel 2: fused GEMM + top-2 + softmax + scatter.
// CTA = 32 tokens x 64 experts x K=2048. 32 warps: (wm, wn2, wk8).
// ---------------------------------------------------------------------------
__global__ __launch_bounds__(NTHR) void gemm_kernel(const float* __restrict__ t1,
                                                    const float* __restrict__ t2,
                                                    float* __restrict__ out) {
    extern __shared__ char smem[];
    const uint32_t sb = smem_u32(smem);
    const int tid  = threadIdx.x;
    const int lane = tid & 31;
    const int wid  = tid >> 5;
    const int wk   = wid & 7;        // k16 slice within 128-wide chunk pair
    const int wn2  = (wid >> 3) & 1; // n32 half
    const int wm   = wid >> 4;       // m16 half
    const int cofs = wk >> 2;        // which chunk of the pair
    const int ks   = wk & 3;         // k16 slice within the 64-wide chunk
    const int tokBase = blockIdx.x * TILE_M;

    const uint32_t aoff = (uint32_t)((wm * 16 + (lane & 15)) * RPITCH
                                     + (lane >> 4) * 16 + ks * 32);
    const uint32_t boff0 = (uint32_t)((wn2 * 32 + ((lane & 7) | ((lane >> 4) << 3))) * RPITCH
                                      + ((lane >> 3) & 1) * 16 + ks * 32);
    const uint32_t boff1 = boff0 + 16 * RPITCH;

    // staging: thread group g stages chunk (pair*2 + g)
    const int g  = tid >> 9;         // 0 or 1
    const int xr = (tid >> 4) & 31;  // X row
    const int xs = tid & 15;         // 4-float segment

    float acc[4][4];
#pragma unroll
    for (int i = 0; i < 4; i++)
#pragma unroll
        for (int j = 0; j < 4; j++) acc[i][j] = 0.f;
    float xq = 0.f;
    float4 rx, rxN;                  // X prefetch, 2 iterations deep

    auto ldgX = [&](float4& dst, int chunk) {
        const int k0 = chunk * KC;
        const float* xsrc = (k0 < D_HALF) ? t1 : t2;
        const int kx = k0 & (D_HALF - 1);
        dst = *(const float4*)(xsrc + (size_t)(tokBase + xr) * D_HALF + kx + xs * 4);
    };
    auto stsX = [&](const float4& v, int buf) {
        uint32_t h0 = pack_bf2(v.x, v.y);
        uint32_t h1 = pack_bf2(v.z, v.w);
        uint32_t l0 = pack_bf2(v.x - __uint_as_float(h0 << 16),
                               v.y - __uint_as_float(h0 & 0xffff0000u));
        uint32_t l1 = pack_bf2(v.z - __uint_as_float(h1 << 16),
                               v.w - __uint_as_float(h1 & 0xffff0000u));
        xq = fmaf(v.x, v.x, xq); xq = fmaf(v.y, v.y, xq);
        xq = fmaf(v.z, v.z, xq); xq = fmaf(v.w, v.w, xq);
        uint32_t xb = sb + (uint32_t)buf * XSTG_B + (uint32_t)(xr * RPITCH + xs * 8);
        sts64(xb + XH_OFF, h0, h1);
        sts64(xb + XL_OFF, l0, l1);
    };
    // One commit group per chunk, ALWAYS committed (empty past the tail)
    // so cp_wait<4> group arithmetic stays uniform. 1 cp16 per thread.
    auto cpW = [&](int chunk) {
        if (chunk < NCHUNK) {
            const int k0 = chunk * KC;
            const uint32_t wb = sb + WBASE + (uint32_t)(chunk & (WSTAGES - 1)) * WSTG_B;
            int half = tid >> 9;              // 0: hi, 1: lo
            int r = (tid >> 3) & 63;
            int c = tid & 7;
            const uint32_t* srcb = half ? g_wl : g_wh;
            cp16(wb + (half ? WL_OFF : WH_OFF) + (uint32_t)(r * RPITCH + c * 16),
                 srcb + ((size_t)r * (KDIM / 2) + (k0 >> 1) + c * 4));
        }
        cp_commit();
    };

    // prologue: X regs for this thread's chunks of pairs 0,1; W groups 0..5
    ldgX(rx,  g);
    ldgX(rxN, g + 2);
    cpW(0); cpW(1); cpW(2); cpW(3); cpW(4); cpW(5);

    for (int it = 0; it < NITER; it++) {
        const int c0 = 2 * it;
        const int cg = c0 + g;       // chunk this thread stages
        stsX(rx, cg & 3);
        rx = rxN;
        if (cg + 4 < NCHUNK) ldgX(rxN, cg + 4);

        cp_wait<4>();                // W groups <= c0+1 complete
        __syncthreads();             // X(c0,c0+1) + W(c0,c0+1) visible
        cpW(c0 + 6);                 // buffers' prior readers done
        cpW(c0 + 7);

        // this warp's chunk and slice
        const int cc = c0 + cofs;
        const uint32_t xb = sb + (uint32_t)(cc & (XSTAGES - 1)) * XSTG_B;
        const uint32_t wb = sb + WBASE + (uint32_t)(cc & (WSTAGES - 1)) * WSTG_B;
        uint32_t ah[4], al[4], bh0[4], bh1[4], bl0[4], bl1[4];
        LDSM4(ah,  xb + XH_OFF + aoff);
        LDSM4(bh0, wb + WH_OFF + boff0);
        LDSM4(bh1, wb + WH_OFF + boff1);
        LDSM4(al,  xb + XL_OFF + aoff);
        LDSM4(bl0, wb + WL_OFF + boff0);
        LDSM4(bl1, wb + WL_OFF + boff1);
        MMA(acc[0], ah, bh0[0], bh0[1]);
        MMA(acc[1], ah, bh0[2], bh0[3]);
        MMA(acc[2], ah, bh1[0], bh1[1]);
        MMA(acc[3], ah, bh1[2], bh1[3]);
        MMA(acc[0], al, bh0[0], bh0[1]);
        MMA(acc[1], al, bh0[2], bh0[3]);
        MMA(acc[2], al, bh1[0], bh1[1]);
        MMA(acc[3], al, bh1[2], bh1[3]);
        MMA(acc[0], ah, bl0[0], bl0[1]);
        MMA(acc[1], ah, bl0[2], bl0[3]);
        MMA(acc[2], ah, bl1[0], bl1[1]);
        MMA(acc[3], ah, bl1[2], bl1[3]);
    }
    __syncthreads();                 // all compute done before smem reuse

    // ---- epilogue: 8 K-split partials -> smem, sum, top-2, scatter ----
    float* kd  = (float*)smem;                 // [8][32][DP]
    float* sxq = kd + 8 * TILE_M * DP;         // [2][32]

    {
        int r0 = wm * 16 + (lane >> 2);
        int cb = wn2 * 32 + (lane & 3) * 2;
#pragma unroll
        for (int t = 0; t < 2; t++)
#pragma unroll
            for (int j = 0; j < 2; j++) {
                const float* a = acc[t * 2 + j];
                int cc2 = cb + t * 16 + j * 8;
                kd[(wk * TILE_M + r0) * DP + cc2]         = a[0];
                kd[(wk * TILE_M + r0) * DP + cc2 + 1]     = a[1];
                kd[(wk * TILE_M + r0 + 8) * DP + cc2]     = a[2];
                kd[(wk * TILE_M + r0 + 8) * DP + cc2 + 1] = a[3];
            }
    }
#pragma unroll
    for (int o = 8; o; o >>= 1) xq += __shfl_xor_sync(0xffffffffu, xq, o);
    if ((tid & 15) == 0) sxq[g * 32 + xr] = xq;
    __syncthreads();

    const float w0 = g_wsq[lane];
    const float w1 = g_wsq[lane + 32];
    const int e0 = lane, e1 = lane + 32;

    {
        const int rloc = wid;                  // one token per warp
        const int tok = tokBase + rloc;
        float d0 = 0.f, d1 = 0.f;
#pragma unroll
        for (int s = 0; s < 8; s++) {
            d0 += kd[(s * TILE_M + rloc) * DP + e0];
            d1 += kd[(s * TILE_M + rloc) * DP + e1];
        }
        float p0 = fmaf(-2.f, d0, w0);
        float p1 = fmaf(-2.f, d1, w1);

        float v1, v2; int i1, i2;
        if (sless(p0, e0, p1, e1)) { v1 = p0; i1 = e0; v2 = p1; i2 = e1; }
        else                        { v1 = p1; i1 = e1; v2 = p0; i2 = e0; }
#pragma unroll
        for (int off = 16; off > 0; off >>= 1) {
            float u1 = __shfl_xor_sync(0xffffffffu, v1, off);
            int   j1 = __shfl_xor_sync(0xffffffffu, i1, off);
            float u2 = __shfl_xor_sync(0xffffffffu, v2, off);
            int   j2 = __shfl_xor_sync(0xffffffffu, i2, off);
            float n1, n2; int m1, m2;
            if (sless(u1, j1, v1, i1)) {
                n1 = u1; m1 = j1;
                if (sless(v1, i1, u2, j2)) { n2 = v1; m2 = i1; }
                else                        { n2 = u2; m2 = j2; }
            } else {
                n1 = v1; m1 = i1;
                if (sless(u1, j1, v2, i2)) { n2 = u1; m2 = j1; }
                else                        { n2 = v2; m2 = i2; }
            }
            v1 = n1; i1 = m1; v2 = n2; i2 = m2;
        }

        const float xqv = sxq[rloc] + sxq[32 + rloc];
        float s1 = xqv + v1; s1 = s1 > 0.f ? s1 : 0.f;
        float s2 = xqv + v2; s2 = s2 > 0.f ? s2 : 0.f;
        const float lg1 = -__fsqrt_rn(s1);
        const float lg2 = -__fsqrt_rn(s2);
        const float ed  = __expf(lg2 - lg1);
        const float inv = 1.f / (1.f + ed);
        const float ga  = inv;
        const float gb  = ed * inv;

        float o0 = (e0 == i1) ? ga : ((e0 == i2) ? gb : 0.f);
        float o1 = (e1 == i1) ? ga : ((e1 == i2) ? gb : 0.f);
        out[(size_t)tok * NEXP + e0] = o0;
        out[(size_t)tok * NEXP + e1] = o1;
    }
}

// ---------------------------------------------------------------------------
extern "C" void kernel_launch(void* const* d_in, const int* in_sizes, int n_in,
                              void* d_out, int out_size) {
    const float* t1 = (const float*)d_in[0];
    const float* t2 = (const float*)d_in[1];
    const float* w  = (const float*)d_in[2];
    float* out = (float*)d_out;

    cudaFuncSetAttribute(gemm_kernel,
                         cudaFuncAttributeMaxDynamicSharedMemorySize, SMEM_TOTAL);

    wsplit_kernel<<<NEXP, 256>>>(w);
    gemm_kernel<<<B_TOK / TILE_M, NTHR, SMEM_TOTAL>>>(t1, t2, out);
}

// round 16
// speedup vs baseline: 1.0838x; 1.0240x over previous
#include <cuda_runtime.h>
#include <cstdint>

// GatingNetwork: B=4096 tokens, x=concat(t1,t2) -> K=2048, E=64 experts.
// logits[b,e] = -sqrt(||w_e - x_b||^2); top-2 softmax scattered into (B,E).
//
// Round 13: warp-specialized producer/consumer, ALL barriers parity-split.
//  - 16 consumer warps (512 thr): pure LDSM+MMA, R9 tiling (wm2 x wn2 x wk4).
//  - 8 producer warps (256 thr): X LDG->bf16 split->STS, W cp.async, xsq.
//  - named barriers (all count 768):
//      full_even=1 / full_odd=4 : producer arrives 256, consumer syncs 512.
//      empty_even=2 / empty_odd=3: consumer arrives 512, producer syncs 256
//                                  at it+2 (2-iteration pipeline distance).
//    Parity split on BOTH pairs guarantees one phase outstanding per barrier:
//    a second arrival into any parity barrier is gated through the opposite
//    barrier's release (R11 deadlocked, R12 raced from exactly this drift).
// dot = xh*wh + xh*wl + xl*wh in fp32; exact fp32 ||x||^2 / ||w||^2.

#define B_TOK   4096
#define D_HALF  1024
#define KDIM    2048
#define NEXP    64
#define TILE_M  32
#define KC      64
#define NCHUNK  (KDIM / KC)       // 32
#define NITER   (NCHUNK / 2)      // 16
#define NTHR    768
#define XSTAGES 4
#define WSTAGES 8

#define RPITCH  144               // 64 bf16 = 128B + 16B pad (LDSM conflict-free)
#define XSTG_B  (2 * TILE_M * RPITCH)         // 9216 (hi+lo, 32 rows)
#define XH_OFF  0
#define XL_OFF  (TILE_M * RPITCH)             // 4608
#define WSTG_B  (2 * NEXP * RPITCH)           // 18432
#define WH_OFF  0
#define WL_OFF  (NEXP * RPITCH)               // 9216
#define WBASE   (XSTAGES * XSTG_B)            // 36864
#define SMEM_TOTAL (WBASE + WSTAGES * WSTG_B) // 184320
#define DP      68                // dots pitch (floats)

__device__ uint32_t g_wh[NEXP * KDIM / 2];   // bf16x2 packed
__device__ uint32_t g_wl[NEXP * KDIM / 2];
__device__ float    g_wsq[NEXP];

// ---------------------------------------------------------------------------
__device__ __forceinline__ uint32_t smem_u32(const void* p) {
    uint32_t a;
    asm("{ .reg .u64 t; cvta.to.shared.u64 t, %1; cvt.u32.u64 %0, t; }"
        : "=r"(a) : "l"(p));
    return a;
}
__device__ __forceinline__ void cp16(uint32_t dst, const void* src) {
    asm volatile("cp.async.cg.shared.global [%0], [%1], 16;" :: "r"(dst), "l"(src));
}
__device__ __forceinline__ void cp_commit() { asm volatile("cp.async.commit_group;"); }
template <int N>
__device__ __forceinline__ void cp_wait() {
    asm volatile("cp.async.wait_group %0;" :: "n"(N));
}
__device__ __forceinline__ void bar_sync(int id) {
    asm volatile("bar.sync %0, %1;" :: "r"(id), "n"(NTHR) : "memory");
}
__device__ __forceinline__ void bar_arrive(int id) {
    asm volatile("bar.arrive %0, %1;" :: "r"(id), "n"(NTHR) : "memory");
}
__device__ __forceinline__ uint32_t pack_bf2(float lo, float hi) {
    uint32_t d;
    asm("cvt.rn.bf16x2.f32 %0, %1, %2;" : "=r"(d) : "f"(hi), "f"(lo));
    return d;
}
__device__ __forceinline__ void sts64(uint32_t a, uint32_t v0, uint32_t v1) {
    asm volatile("st.shared.v2.b32 [%0], {%1,%2};"
                 :: "r"(a), "r"(v0), "r"(v1) : "memory");
}

#define LDSM4(r, addr) \
    asm volatile("ldmatrix.sync.aligned.m8n8.x4.shared.b16 {%0,%1,%2,%3}, [%4];" \
        : "=r"((r)[0]), "=r"((r)[1]), "=r"((r)[2]), "=r"((r)[3]) : "r"(addr))

#define MMA(c, a, b0_, b1_) \
    asm volatile("mma.sync.aligned.m16n8k16.row.col.f32.bf16.bf16.f32 " \
        "{%0,%1,%2,%3}, {%4,%5,%6,%7}, {%8,%9}, {%0,%1,%2,%3};" \
        : "+f"((c)[0]), "+f"((c)[1]), "+f"((c)[2]), "+f"((c)[3]) \
        : "r"((a)[0]), "r"((a)[1]), "r"((a)[2]), "r"((a)[3]), "r"(b0_), "r"(b1_))

__device__ __forceinline__ bool sless(float a, int ia, float b, int ib) {
    return (a < b) || (a == b && ia < ib);
}

// ---------------------------------------------------------------------------
// Kernel 1: split W into bf16 hi/lo, exact ||w||^2.
// ---------------------------------------------------------------------------
__global__ __launch_bounds__(256) void wsplit_kernel(const float* __restrict__ w) {
    const int row = blockIdx.x;
    const int t = threadIdx.x;
    const float4* src = (const float4*)(w + (size_t)row * KDIM);
    float q = 0.f;
    for (int i = t; i < KDIM / 4; i += 256) {
        float4 v = src[i];
        uint32_t h0 = pack_bf2(v.x, v.y);
        uint32_t h1 = pack_bf2(v.z, v.w);
        float r0 = v.x - __uint_as_float(h0 << 16);
        float r1 = v.y - __uint_as_float(h0 & 0xffff0000u);
        float r2 = v.z - __uint_as_float(h1 << 16);
        float r3 = v.w - __uint_as_float(h1 & 0xffff0000u);
        uint32_t l0 = pack_bf2(r0, r1);
        uint32_t l1 = pack_bf2(r2, r3);
        q = fmaf(v.x, v.x, q); q = fmaf(v.y, v.y, q);
        q = fmaf(v.z, v.z, q); q = fmaf(v.w, v.w, q);
        g_wh[row * (KDIM / 2) + 2 * i]     = h0;
        g_wh[row * (KDIM / 2) + 2 * i + 1] = h1;
        g_wl[row * (KDIM / 2) + 2 * i]     = l0;
        g_wl[row * (KDIM / 2) + 2 * i + 1] = l1;
    }
#pragma unroll
    for (int o = 16; o; o >>= 1) q += __shfl_xor_sync(0xffffffffu, q, o);
    __shared__ float red[8];
    if ((t & 31) == 0) red[t >> 5] = q;
    __syncthreads();
    if (t == 0) {
        float s = 0.f;
#pragma unroll
        for (int i = 0; i < 8; i++) s += red[i];
        g_wsq[row] = s;
    }
}

// ---------------------------------------------------------------------------
// Kernel 2: warp-specialized fused GEMM + top-2 + softmax + scatter.
// ---------------------------------------------------------------------------
__global__ __launch_bounds__(NTHR) void gemm_kernel(const float* __restrict__ t1,
                                                    const float* __restrict__ t2,
                                                    float* __restrict__ out) {
    extern __shared__ char smem[];
    const uint32_t sb = smem_u32(smem);
    const int tid  = threadIdx.x;
    const int lane = tid & 31;
    const int wid  = tid >> 5;
    const int tokBase = blockIdx.x * TILE_M;

    float* kd  = (float*)smem;                 // [4][32][DP] (epilogue)
    float* sxq = kd + 4 * TILE_M * DP;         // [32]

    float acc[4][4];
#pragma unroll
    for (int i = 0; i < 4; i++)
#pragma unroll
        for (int j = 0; j < 4; j++) acc[i][j] = 0.f;
    float xq = 0.f;

    if (wid < 16) {
        // =========================== CONSUMERS ===========================
        const int wk  = wid & 3;
        const int wn2 = (wid >> 2) & 1;
        const int wm  = wid >> 3;
        const uint32_t aoff = (uint32_t)((wm * 16 + (lane & 15)) * RPITCH
                                         + (lane >> 4) * 16 + wk * 32);
        const uint32_t boff0 = (uint32_t)((wn2 * 32 + ((lane & 7) | ((lane >> 4) << 3))) * RPITCH
                                          + ((lane >> 3) & 1) * 16 + wk * 32);
        const uint32_t boff1 = boff0 + 16 * RPITCH;

        for (int it = 0; it < NITER; it++) {
            bar_sync((it & 1) ? 4 : 1);       // wait: producer staged 2it, 2it+1
#pragma unroll
            for (int h = 0; h < 2; h++) {
                const int c = 2 * it + h;
                const uint32_t xb = sb + (uint32_t)(c & (XSTAGES - 1)) * XSTG_B;
                const uint32_t wb = sb + WBASE + (uint32_t)(c & (WSTAGES - 1)) * WSTG_B;
                uint32_t ah[4], al[4], bh0[4], bh1[4], bl0[4], bl1[4];
                LDSM4(ah,  xb + XH_OFF + aoff);
                LDSM4(bh0, wb + WH_OFF + boff0);
                LDSM4(bh1, wb + WH_OFF + boff1);
                LDSM4(al,  xb + XL_OFF + aoff);
                LDSM4(bl0, wb + WL_OFF + boff0);
                LDSM4(bl1, wb + WL_OFF + boff1);
                MMA(acc[0], ah, bh0[0], bh0[1]);
                MMA(acc[1], ah, bh0[2], bh0[3]);
                MMA(acc[2], ah, bh1[0], bh1[1]);
                MMA(acc[3], ah, bh1[2], bh1[3]);
                MMA(acc[0], al, bh0[0], bh0[1]);
                MMA(acc[1], al, bh0[2], bh0[3]);
                MMA(acc[2], al, bh1[0], bh1[1]);
                MMA(acc[3], al, bh1[2], bh1[3]);
                MMA(acc[0], ah, bl0[0], bl0[1]);
                MMA(acc[1], ah, bl0[2], bl0[3]);
                MMA(acc[2], ah, bl1[0], bl1[1]);
                MMA(acc[3], ah, bl1[2], bl1[3]);
            }
            bar_arrive(2 + (it & 1));         // signal: iteration it consumed
        }
    } else {
        // =========================== PRODUCERS ===========================
        const int p  = tid - 512;             // 0..255
        const int xr = p >> 3;                // token row 0..31
        const int xs = p & 7;                 // seg-pair index (segs 2xs, 2xs+1)

        float4 rxc[4], rxn[4];                // current / next iteration X regs

        auto ldgX = [&](float4* dst, int it) {
            // iteration it covers chunks 2it (elems [0..1]) and 2it+1 ([2..3])
#pragma unroll
            for (int h = 0; h < 2; h++) {
                const int k0 = (2 * it + h) * KC;
                const float* xsrc = (k0 < D_HALF) ? t1 : t2;
                const int kx = k0 & (D_HALF - 1);
                const float4* xp = (const float4*)(xsrc + (size_t)(tokBase + xr) * D_HALF
                                                   + kx + xs * 8);
                dst[2 * h]     = xp[0];
                dst[2 * h + 1] = xp[1];
            }
        };
        auto stsX = [&](const float4* v, int it) {
#pragma unroll
            for (int h = 0; h < 2; h++) {
                const int c = 2 * it + h;
                const uint32_t xb = sb + (uint32_t)(c & (XSTAGES - 1)) * XSTG_B
                                    + (uint32_t)(xr * RPITCH + xs * 16);
#pragma unroll
                for (int e = 0; e < 2; e++) {
                    float4 vv = v[2 * h + e];
                    uint32_t h0 = pack_bf2(vv.x, vv.y);
                    uint32_t h1 = pack_bf2(vv.z, vv.w);
                    uint32_t l0 = pack_bf2(vv.x - __uint_as_float(h0 << 16),
                                           vv.y - __uint_as_float(h0 & 0xffff0000u));
                    uint32_t l1 = pack_bf2(vv.z - __uint_as_float(h1 << 16),
                                           vv.w - __uint_as_float(h1 & 0xffff0000u));
                    xq = fmaf(vv.x, vv.x, xq); xq = fmaf(vv.y, vv.y, xq);
                    xq = fmaf(vv.z, vv.z, xq); xq = fmaf(vv.w, vv.w, xq);
                    sts64(xb + XH_OFF + e * 8, h0, h1);
                    sts64(xb + XL_OFF + e * 8, l0, l1);
                }
            }
        };
        // one commit group per chunk; ALWAYS committed (empty past tail)
        auto cpW = [&](int chunk) {
            if (chunk < NCHUNK) {
                const int k0 = chunk * KC;
                const uint32_t wb = sb + WBASE
                                    + (uint32_t)(chunk & (WSTAGES - 1)) * WSTG_B;
#pragma unroll
                for (int j = 0; j < 4; j++) {
                    int i = p + 256 * j;              // 0..1023
                    int half = i >> 9;                // 0: hi, 1: lo
                    int r = (i >> 3) & 63;
                    int c = i & 7;
                    const uint32_t* srcb = half ? g_wl : g_wh;
                    cp16(wb + (half ? WL_OFF : WH_OFF) + (uint32_t)(r * RPITCH + c * 16),
                         srcb + ((size_t)r * (KDIM / 2) + (k0 >> 1) + c * 4));
                }
            }
            cp_commit();
        };

        // prologue: X regs for it=0; W groups for chunks 0..3
        ldgX(rxc, 0);
        cpW(0); cpW(1); cpW(2); cpW(3);

        for (int it = 0; it < NITER; it++) {
            if (it >= 2) bar_sync(2 + (it & 1));  // consumers finished it-2
            cpW(2 * it + 4);                      // W for iteration it+2
            cpW(2 * it + 5);
            if (it + 1 < NITER) ldgX(rxn, it + 1);
            stsX(rxc, it);
            cp_wait<4>();                         // W chunks 2it, 2it+1 landed
            __threadfence_block();                // publish STS + cp.async writes
            bar_arrive((it & 1) ? 4 : 1);         // iteration it full
#pragma unroll
            for (int e = 0; e < 4; e++) rxc[e] = rxn[e];
        }
    }

    __syncthreads();                           // everyone done; smem reusable

    // ---- epilogue ----
    if (wid < 16) {
        const int wk  = wid & 3;
        const int wn2 = (wid >> 2) & 1;
        const int wm  = wid >> 3;
        int r0 = wm * 16 + (lane >> 2);
        int cb = wn2 * 32 + (lane & 3) * 2;
#pragma unroll
        for (int t = 0; t < 2; t++)
#pragma unroll
            for (int j = 0; j < 2; j++) {
                const float* a = acc[t * 2 + j];
                int cc = cb + t * 16 + j * 8;
                kd[(wk * TILE_M + r0) * DP + cc]           = a[0];
                kd[(wk * TILE_M + r0) * DP + cc + 1]       = a[1];
                kd[(wk * TILE_M + r0 + 8) * DP + cc]       = a[2];
                kd[(wk * TILE_M + r0 + 8) * DP + cc + 1]   = a[3];
            }
    } else {
        const int p = tid - 512;
#pragma unroll
        for (int o = 4; o; o >>= 1) xq += __shfl_xor_sync(0xffffffffu, xq, o);
        if ((p & 7) == 0) sxq[p >> 3] = xq;
    }
    __syncthreads();

    if (wid < 16) {
        const float w0 = g_wsq[lane];
        const float w1 = g_wsq[lane + 32];
        const int e0 = lane, e1 = lane + 32;
#pragma unroll
        for (int tt = 0; tt < 2; tt++) {
            const int rloc = wid * 2 + tt;
            const int tok = tokBase + rloc;
            float d0 = (kd[(0 * TILE_M + rloc) * DP + e0] + kd[(1 * TILE_M + rloc) * DP + e0])
                     + (kd[(2 * TILE_M + rloc) * DP + e0] + kd[(3 * TILE_M + rloc) * DP + e0]);
            float d1 = (kd[(0 * TILE_M + rloc) * DP + e1] + kd[(1 * TILE_M + rloc) * DP + e1])
                     + (kd[(2 * TILE_M + rloc) * DP + e1] + kd[(3 * TILE_M + rloc) * DP + e1]);
            float p0 = fmaf(-2.f, d0, w0);
            float p1 = fmaf(-2.f, d1, w1);

            float v1, v2; int i1, i2;
            if (sless(p0, e0, p1, e1)) { v1 = p0; i1 = e0; v2 = p1; i2 = e1; }
            else                        { v1 = p1; i1 = e1; v2 = p0; i2 = e0; }
#pragma unroll
            for (int off = 16; off > 0; off >>= 1) {
                float u1 = __shfl_xor_sync(0xffffffffu, v1, off);
                int   j1 = __shfl_xor_sync(0xffffffffu, i1, off);
                float u2 = __shfl_xor_sync(0xffffffffu, v2, off);
                int   j2 = __shfl_xor_sync(0xffffffffu, i2, off);
                float n1, n2; int m1, m2;
                if (sless(u1, j1, v1, i1)) {
                    n1 = u1; m1 = j1;
                    if (sless(v1, i1, u2, j2)) { n2 = v1; m2 = i1; }
                    else                        { n2 = u2; m2 = j2; }
                } else {
                    n1 = v1; m1 = i1;
                    if (sless(u1, j1, v2, i2)) { n2 = u1; m2 = j1; }
                    else                        { n2 = v2; m2 = i2; }
                }
                v1 = n1; i1 = m1; v2 = n2; i2 = m2;
            }

            const float xqv = sxq[rloc];
            float s1 = xqv + v1; s1 = s1 > 0.f ? s1 : 0.f;
            float s2 = xqv + v2; s2 = s2 > 0.f ? s2 : 0.f;
            const float lg1 = -__fsqrt_rn(s1);
            const float lg2 = -__fsqrt_rn(s2);
            const float ed  = __expf(lg2 - lg1);
            const float inv = 1.f / (1.f + ed);
            const float ga  = inv;
            const float gb  = ed * inv;

            float o0 = (e0 == i1) ? ga : ((e0 == i2) ? gb : 0.f);
            float o1 = (e1 == i1) ? ga : ((e1 == i2) ? gb : 0.f);
            out[(size_t)tok * NEXP + e0] = o0;
            out[(size_t)tok * NEXP + e1] = o1;
        }
    }
}

// ---------------------------------------------------------------------------
extern "C" void kernel_launch(void* const* d_in, const int* in_sizes, int n_in,
                              void* d_out, int out_size) {
    const float* t1 = (const float*)d_in[0];
    const float* t2 = (const float*)d_in[1];
    const float* w  = (const float*)d_in[2];
    float* out = (float*)d_out;

    cudaFuncSetAttribute(gemm_kernel,
                         cudaFuncAttributeMaxDynamicSharedMemorySize, SMEM_TOTAL);

    wsplit_kernel<<<NEXP, 256>>>(w);
    gemm_kernel<<<B_TOK / TILE_M, NTHR, SMEM_TOTAL>>>(t1, t2, out);
}

// round 17
// speedup vs baseline: 1.1104x; 1.0245x over previous
#include <cuda_runtime.h>
#include <cstdint>

// GatingNetwork: B=4096 tokens, x=concat(t1,t2) -> K=2048, E=64 experts.
// logits[b,e] = -sqrt(||w_e - x_b||^2); top-2 softmax scattered into (B,E).
//
// Round 16: R13 producer/consumer + WIDER consumer warp tiles (m32 x n32):
// 16 consumer warps = (2 n32 halves) x (8 k16 slices of each k128 pair).
// Each B fragment now read by exactly ONE warp -> LDSM traffic 96->64KB per
// k128 (-33%), same MMA count. Producer + 4-parity-barrier protocol
// unchanged from the passing R13.
// dot = xh*wh + xh*wl + xl*wh in fp32; exact fp32 ||x||^2 / ||w||^2.

#define B_TOK   4096
#define D_HALF  1024
#define KDIM    2048
#define NEXP    64
#define TILE_M  32
#define KC      64
#define NCHUNK  (KDIM / KC)       // 32
#define NITER   (NCHUNK / 2)      // 16
#define NTHR    768
#define XSTAGES 4
#define WSTAGES 8

#define RPITCH  144               // 64 bf16 = 128B + 16B pad (LDSM conflict-free)
#define XSTG_B  (2 * TILE_M * RPITCH)         // 9216 (hi+lo, 32 rows)
#define XH_OFF  0
#define XL_OFF  (TILE_M * RPITCH)             // 4608
#define WSTG_B  (2 * NEXP * RPITCH)           // 18432
#define WH_OFF  0
#define WL_OFF  (NEXP * RPITCH)               // 9216
#define WBASE   (XSTAGES * XSTG_B)            // 36864
#define SMEM_TOTAL (WBASE + WSTAGES * WSTG_B) // 184320
#define DP      68                // dots pitch (floats)

__device__ uint32_t g_wh[NEXP * KDIM / 2];   // bf16x2 packed
__device__ uint32_t g_wl[NEXP * KDIM / 2];
__device__ float    g_wsq[NEXP];

// ---------------------------------------------------------------------------
__device__ __forceinline__ uint32_t smem_u32(const void* p) {
    uint32_t a;
    asm("{ .reg .u64 t; cvta.to.shared.u64 t, %1; cvt.u32.u64 %0, t; }"
        : "=r"(a) : "l"(p));
    return a;
}
__device__ __forceinline__ void cp16(uint32_t dst, const void* src) {
    asm volatile("cp.async.cg.shared.global [%0], [%1], 16;" :: "r"(dst), "l"(src));
}
__device__ __forceinline__ void cp_commit() { asm volatile("cp.async.commit_group;"); }
template <int N>
__device__ __forceinline__ void cp_wait() {
    asm volatile("cp.async.wait_group %0;" :: "n"(N));
}
__device__ __forceinline__ void bar_sync(int id) {
    asm volatile("bar.sync %0, %1;" :: "r"(id), "n"(NTHR) : "memory");
}
__device__ __forceinline__ void bar_arrive(int id) {
    asm volatile("bar.arrive %0, %1;" :: "r"(id), "n"(NTHR) : "memory");
}
__device__ __forceinline__ uint32_t pack_bf2(float lo, float hi) {
    uint32_t d;
    asm("cvt.rn.bf16x2.f32 %0, %1, %2;" : "=r"(d) : "f"(hi), "f"(lo));
    return d;
}
__device__ __forceinline__ void sts64(uint32_t a, uint32_t v0, uint32_t v1) {
    asm volatile("st.shared.v2.b32 [%0], {%1,%2};"
                 :: "r"(a), "r"(v0), "r"(v1) : "memory");
}

#define LDSM4(r, addr) \
    asm volatile("ldmatrix.sync.aligned.m8n8.x4.shared.b16 {%0,%1,%2,%3}, [%4];" \
        : "=r"((r)[0]), "=r"((r)[1]), "=r"((r)[2]), "=r"((r)[3]) : "r"(addr))

#define MMA(c, a, b0_, b1_) \
    asm volatile("mma.sync.aligned.m16n8k16.row.col.f32.bf16.bf16.f32 " \
        "{%0,%1,%2,%3}, {%4,%5,%6,%7}, {%8,%9}, {%0,%1,%2,%3};" \
        : "+f"((c)[0]), "+f"((c)[1]), "+f"((c)[2]), "+f"((c)[3]) \
        : "r"((a)[0]), "r"((a)[1]), "r"((a)[2]), "r"((a)[3]), "r"(b0_), "r"(b1_))

__device__ __forceinline__ bool sless(float a, int ia, float b, int ib) {
    return (a < b) || (a == b && ia < ib);
}

// ---------------------------------------------------------------------------
// Kernel 1: split W into bf16 hi/lo, exact ||w||^2.
// ---------------------------------------------------------------------------
__global__ __launch_bounds__(256) void wsplit_kernel(const float* __restrict__ w) {
    const int row = blockIdx.x;
    const int t = threadIdx.x;
    const float4* src = (const float4*)(w + (size_t)row * KDIM);
    float q = 0.f;
    for (int i = t; i < KDIM / 4; i += 256) {
        float4 v = src[i];
        uint32_t h0 = pack_bf2(v.x, v.y);
        uint32_t h1 = pack_bf2(v.z, v.w);
        float r0 = v.x - __uint_as_float(h0 << 16);
        float r1 = v.y - __uint_as_float(h0 & 0xffff0000u);
        float r2 = v.z - __uint_as_float(h1 << 16);
        float r3 = v.w - __uint_as_float(h1 & 0xffff0000u);
        uint32_t l0 = pack_bf2(r0, r1);
        uint32_t l1 = pack_bf2(r2, r3);
        q = fmaf(v.x, v.x, q); q = fmaf(v.y, v.y, q);
        q = fmaf(v.z, v.z, q); q = fmaf(v.w, v.w, q);
        g_wh[row * (KDIM / 2) + 2 * i]     = h0;
        g_wh[row * (KDIM / 2) + 2 * i + 1] = h1;
        g_wl[row * (KDIM / 2) + 2 * i]     = l0;
        g_wl[row * (KDIM / 2) + 2 * i + 1] = l1;
    }
#pragma unroll
    for (int o = 16; o; o >>= 1) q += __shfl_xor_sync(0xffffffffu, q, o);
    __shared__ float red[8];
    if ((t & 31) == 0) red[t >> 5] = q;
    __syncthreads();
    if (t == 0) {
        float s = 0.f;
#pragma unroll
        for (int i = 0; i < 8; i++) s += red[i];
        g_wsq[row] = s;
    }
}

// ---------------------------------------------------------------------------
// Kernel 2: warp-specialized fused GEMM + top-2 + softmax + scatter.
// ---------------------------------------------------------------------------
__global__ __launch_bounds__(NTHR) void gemm_kernel(const float* __restrict__ t1,
                                                    const float* __restrict__ t2,
                                                    float* __restrict__ out) {
    extern __shared__ char smem[];
    const uint32_t sb = smem_u32(smem);
    const int tid  = threadIdx.x;
    const int lane = tid & 31;
    const int wid  = tid >> 5;
    const int tokBase = blockIdx.x * TILE_M;

    float* kd  = (float*)smem;                 // [8][32][DP] (epilogue)
    float* sxq = kd + 8 * TILE_M * DP;         // [32]

    float acc[8][4];                           // [mi*4+nj][4]: m32 x n32
#pragma unroll
    for (int i = 0; i < 8; i++)
#pragma unroll
        for (int j = 0; j < 4; j++) acc[i][j] = 0.f;
    float xq = 0.f;

    if (wid < 16) {
        // =========================== CONSUMERS ===========================
        // warp = (wn2: n32 half) x (wk: k16 slice of the k128 pair)
        const int wk  = wid & 7;         // 0..7: slice of k128
        const int wn2 = wid >> 3;        // n32 half
        const int cofs = wk >> 2;        // which chunk of the pair
        const int ks   = wk & 3;         // k16 slice within the chunk

        const uint32_t aoff0 = (uint32_t)((lane & 15) * RPITCH
                                          + (lane >> 4) * 16 + ks * 32);
        const uint32_t aoff1 = aoff0 + 16 * RPITCH;
        const uint32_t boff0 = (uint32_t)((wn2 * 32 + ((lane & 7) | ((lane >> 4) << 3))) * RPITCH
                                          + ((lane >> 3) & 1) * 16 + ks * 32);
        const uint32_t boff1 = boff0 + 16 * RPITCH;

        for (int it = 0; it < NITER; it++) {
            bar_sync((it & 1) ? 4 : 1);       // wait: producer staged 2it, 2it+1
            const int c = 2 * it + cofs;
            const uint32_t xb = sb + (uint32_t)(c & (XSTAGES - 1)) * XSTG_B;
            const uint32_t wb = sb + WBASE + (uint32_t)(c & (WSTAGES - 1)) * WSTG_B;

            uint32_t ah0[4], ah1[4], al0[4], al1[4], b0[4], b1[4];
            LDSM4(ah0, xb + XH_OFF + aoff0);
            LDSM4(ah1, xb + XH_OFF + aoff1);
            LDSM4(al0, xb + XL_OFF + aoff0);
            LDSM4(al1, xb + XL_OFF + aoff1);
            LDSM4(b0,  wb + WH_OFF + boff0);
            LDSM4(b1,  wb + WH_OFF + boff1);
            // hi*hi and lo*hi
            MMA(acc[0], ah0, b0[0], b0[1]);
            MMA(acc[1], ah0, b0[2], b0[3]);
            MMA(acc[2], ah0, b1[0], b1[1]);
            MMA(acc[3], ah0, b1[2], b1[3]);
            MMA(acc[4], ah1, b0[0], b0[1]);
            MMA(acc[5], ah1, b0[2], b0[3]);
            MMA(acc[6], ah1, b1[0], b1[1]);
            MMA(acc[7], ah1, b1[2], b1[3]);
            MMA(acc[0], al0, b0[0], b0[1]);
            MMA(acc[1], al0, b0[2], b0[3]);
            MMA(acc[2], al0, b1[0], b1[1]);
            MMA(acc[3], al0, b1[2], b1[3]);
            MMA(acc[4], al1, b0[0], b0[1]);
            MMA(acc[5], al1, b0[2], b0[3]);
            MMA(acc[6], al1, b1[0], b1[1]);
            MMA(acc[7], al1, b1[2], b1[3]);
            // hi*lo
            LDSM4(b0, wb + WL_OFF + boff0);
            LDSM4(b1, wb + WL_OFF + boff1);
            MMA(acc[0], ah0, b0[0], b0[1]);
            MMA(acc[1], ah0, b0[2], b0[3]);
            MMA(acc[2], ah0, b1[0], b1[1]);
            MMA(acc[3], ah0, b1[2], b1[3]);
            MMA(acc[4], ah1, b0[0], b0[1]);
            MMA(acc[5], ah1, b0[2], b0[3]);
            MMA(acc[6], ah1, b1[0], b1[1]);
            MMA(acc[7], ah1, b1[2], b1[3]);

            bar_arrive(2 + (it & 1));         // signal: iteration it consumed
        }
    } else {
        // =========================== PRODUCERS ===========================
        const int p  = tid - 512;             // 0..255
        const int xr = p >> 3;                // token row 0..31
        const int xs = p & 7;                 // seg-pair index (segs 2xs, 2xs+1)

        float4 rxc[4], rxn[4];                // current / next iteration X regs

        auto ldgX = [&](float4* dst, int it) {
#pragma unroll
            for (int h = 0; h < 2; h++) {
                const int k0 = (2 * it + h) * KC;
                const float* xsrc = (k0 < D_HALF) ? t1 : t2;
                const int kx = k0 & (D_HALF - 1);
                const float4* xp = (const float4*)(xsrc + (size_t)(tokBase + xr) * D_HALF
                                                   + kx + xs * 8);
                dst[2 * h]     = xp[0];
                dst[2 * h + 1] = xp[1];
            }
        };
        auto stsX = [&](const float4* v, int it) {
#pragma unroll
            for (int h = 0; h < 2; h++) {
                const int c = 2 * it + h;
                const uint32_t xb = sb + (uint32_t)(c & (XSTAGES - 1)) * XSTG_B
                                    + (uint32_t)(xr * RPITCH + xs * 16);
#pragma unroll
                for (int e = 0; e < 2; e++) {
                    float4 vv = v[2 * h + e];
                    uint32_t h0 = pack_bf2(vv.x, vv.y);
                    uint32_t h1 = pack_bf2(vv.z, vv.w);
                    uint32_t l0 = pack_bf2(vv.x - __uint_as_float(h0 << 16),
                                           vv.y - __uint_as_float(h0 & 0xffff0000u));
                    uint32_t l1 = pack_bf2(vv.z - __uint_as_float(h1 << 16),
                                           vv.w - __uint_as_float(h1 & 0xffff0000u));
                    xq = fmaf(vv.x, vv.x, xq); xq = fmaf(vv.y, vv.y, xq);
                    xq = fmaf(vv.z, vv.z, xq); xq = fmaf(vv.w, vv.w, xq);
                    sts64(xb + XH_OFF + e * 8, h0, h1);
                    sts64(xb + XL_OFF + e * 8, l0, l1);
                }
            }
        };
        // one commit group per chunk; ALWAYS committed (empty past tail)
        auto cpW = [&](int chunk) {
            if (chunk < NCHUNK) {
                const int k0 = chunk * KC;
                const uint32_t wb = sb + WBASE
                                    + (uint32_t)(chunk & (WSTAGES - 1)) * WSTG_B;
#pragma unroll
                for (int j = 0; j < 4; j++) {
                    int i = p + 256 * j;              // 0..1023
                    int half = i >> 9;                // 0: hi, 1: lo
                    int r = (i >> 3) & 63;
                    int c = i & 7;
                    const uint32_t* srcb = half ? g_wl : g_wh;
                    cp16(wb + (half ? WL_OFF : WH_OFF) + (uint32_t)(r * RPITCH + c * 16),
                         srcb + ((size_t)r * (KDIM / 2) + (k0 >> 1) + c * 4));
                }
            }
            cp_commit();
        };

        // prologue: X regs for it=0; W groups for chunks 0..3
        ldgX(rxc, 0);
        cpW(0); cpW(1); cpW(2); cpW(3);

        for (int it = 0; it < NITER; it++) {
            if (it >= 2) bar_sync(2 + (it & 1));  // consumers finished it-2
            cpW(2 * it + 4);                      // W for iteration it+2
            cpW(2 * it + 5);
            if (it + 1 < NITER) ldgX(rxn, it + 1);
            stsX(rxc, it);
            cp_wait<4>();                         // W chunks 2it, 2it+1 landed
            __threadfence_block();                // publish STS + cp.async writes
            bar_arrive((it & 1) ? 4 : 1);         // iteration it full
#pragma unroll
            for (int e = 0; e < 4; e++) rxc[e] = rxn[e];
        }
    }

    __syncthreads();                           // everyone done; smem reusable

    // ---- epilogue: 8 k16-partials -> smem, sum, top-2, scatter ----
    if (wid < 16) {
        const int wk  = wid & 7;
        const int wn2 = wid >> 3;
        int rr = lane >> 2;
        int cb = wn2 * 32 + (lane & 3) * 2;
#pragma unroll
        for (int mi = 0; mi < 2; mi++)
#pragma unroll
            for (int nj = 0; nj < 4; nj++) {
                const float* a = acc[mi * 4 + nj];
                int row = mi * 16 + rr;
                int cc  = cb + nj * 8;
                kd[(wk * TILE_M + row) * DP + cc]           = a[0];
                kd[(wk * TILE_M + row) * DP + cc + 1]       = a[1];
                kd[(wk * TILE_M + row + 8) * DP + cc]       = a[2];
                kd[(wk * TILE_M + row + 8) * DP + cc + 1]   = a[3];
            }
    } else {
        const int p = tid - 512;
#pragma unroll
        for (int o = 4; o; o >>= 1) xq += __shfl_xor_sync(0xffffffffu, xq, o);
        if ((p & 7) == 0) sxq[p >> 3] = xq;
    }
    __syncthreads();

    if (wid < 16) {
        const float w0 = g_wsq[lane];
        const float w1 = g_wsq[lane + 32];
        const int e0 = lane, e1 = lane + 32;
#pragma unroll
        for (int tt = 0; tt < 2; tt++) {
            const int rloc = wid * 2 + tt;
            const int tok = tokBase + rloc;
            float d0 = 0.f, d1 = 0.f;
#pragma unroll
            for (int s = 0; s < 8; s++) {
                d0 += kd[(s * TILE_M + rloc) * DP + e0];
                d1 += kd[(s * TILE_M + rloc) * DP + e1];
            }
            float p0 = fmaf(-2.f, d0, w0);
            float p1 = fmaf(-2.f, d1, w1);

            float v1, v2; int i1, i2;
            if (sless(p0, e0, p1, e1)) { v1 = p0; i1 = e0; v2 = p1; i2 = e1; }
            else                        { v1 = p1; i1 = e1; v2 = p0; i2 = e0; }
#pragma unroll
            for (int off = 16; off > 0; off >>= 1) {
                float u1 = __shfl_xor_sync(0xffffffffu, v1, off);
                int   j1 = __shfl_xor_sync(0xffffffffu, i1, off);
                float u2 = __shfl_xor_sync(0xffffffffu, v2, off);
                int   j2 = __shfl_xor_sync(0xffffffffu, i2, off);
                float n1, n2; int m1, m2;
                if (sless(u1, j1, v1, i1)) {
                    n1 = u1; m1 = j1;
                    if (sless(v1, i1, u2, j2)) { n2 = v1; m2 = i1; }
                    else                        { n2 = u2; m2 = j2; }
                } else {
                    n1 = v1; m1 = i1;
                    if (sless(u1, j1, v2, i2)) { n2 = u1; m2 = j1; }
                    else                        { n2 = v2; m2 = i2; }
                }
                v1 = n1; i1 = m1; v2 = n2; i2 = m2;
            }

            const float xqv = sxq[rloc];
            float s1 = xqv + v1; s1 = s1 > 0.f ? s1 : 0.f;
            float s2 = xqv + v2; s2 = s2 > 0.f ? s2 : 0.f;
            const float lg1 = -__fsqrt_rn(s1);
            const float lg2 = -__fsqrt_rn(s2);
            const float ed  = __expf(lg2 - lg1);
            const float inv = 1.f / (1.f + ed);
            const float ga  = inv;
            const float gb  = ed * inv;

            float o0 = (e0 == i1) ? ga : ((e0 == i2) ? gb : 0.f);
            float o1 = (e1 == i1) ? ga : ((e1 == i2) ? gb : 0.f);
            out[(size_t)tok * NEXP + e0] = o0;
            out[(size_t)tok * NEXP + e1] = o1;
        }
    }
}

// ---------------------------------------------------------------------------
extern "C" void kernel_launch(void* const* d_in, const int* in_sizes, int n_in,
                              void* d_out, int out_size) {
    const float* t1 = (const float*)d_in[0];
    const float* t2 = (const float*)d_in[1];
    const float* w  = (const float*)d_in[2];
    float* out = (float*)d_out;

    cudaFuncSetAttribute(gemm_kernel,
                         cudaFuncAttributeMaxDynamicSharedMemorySize, SMEM_TOTAL);

    wsplit_kernel<<<NEXP, 256>>>(w);
    gemm_kernel<<<B_TOK / TILE_M, NTHR, SMEM_TOTAL>>>(t1, t2, out);
}